// round 10
// baseline (speedup 1.0000x reference)
#include <cuda_runtime.h>
#include <cuda_bf16.h>

// ---------------------------------------------------------------------------
// LaplacianRegularization
//   degree = segment_sum(w, row);  ys = bf16( y * rsqrt(degree)[:,None] )
//   out = mean_e( ||ys[row] - ys[col]||_2 * w_e )
//
// Inputs (metadata order):
//   d_in[0] : edge_index  int64 OR int32 (2, E)   (dtype detected on-device)
//   d_in[1] : edge_weights float32 (E,)
//   d_in[2] : y            float32 (N, 16)
// Output: 1 float
//
// 4 launches: k_probe (dtype), k_degree (atomics), k_scale (rows -> bf16,
// zeroes g_deg for next replay), k_main (octet-gather: 8 lanes per row so
// each gather instruction touches only 4 cache lines -> fewer L1tex replays).
// Scratch invariants are restored in-kernel, so no zeroing pass is needed.
// ---------------------------------------------------------------------------

#define MAX_NODES 131072

__device__ float    g_deg[MAX_NODES];                       // zero-init; re-zeroed by k_scale
__device__ __align__(128) uint4 g_ysb[MAX_NODES * 2];       // bf16 rows: 32B each
__device__ double   g_sum;                                  // reset by k_main finalize
__device__ unsigned g_flag;                                 // !=0 => int32 indices
__device__ unsigned g_count;                                // reset by k_main finalize

__device__ __forceinline__ int load_idx(const void* ei, long long pos, bool is32) {
    if (is32) return ((const int*)ei)[pos];
    return (int)((const long long*)ei)[pos];
}

// --- K0: dtype probe (1 warp) ------------------------------------------------
// int64 indices < 2^31 have zero hi-words; for int32 the odd words are node
// ids, nonzero w.h.p. over 512 samples of U[0, N).
__global__ void k_probe(const unsigned* __restrict__ words, int E) {
    int samples = E < 512 ? E : 512;
    unsigned v = 0;
    for (int i = threadIdx.x; i < samples; i += 32)
        v |= words[2 * i + 1];
    #pragma unroll
    for (int o = 16; o > 0; o >>= 1)
        v |= __shfl_xor_sync(0xFFFFFFFFu, v, o);
    if (threadIdx.x == 0) g_flag = v;
}

// --- K1: degree = segment_sum(w, row) ----------------------------------------
__global__ void k_degree(const void* __restrict__ ei,
                         const float* __restrict__ w, int E, int N) {
    int e = blockIdx.x * blockDim.x + threadIdx.x;
    if (e >= E) return;
    const bool is32 = (g_flag != 0u);
    int r = load_idx(ei, e, is32);
    if ((unsigned)r < (unsigned)N)
        atomicAdd(&g_deg[r], w[e]);
}

// --- K2: ys(bf16) = y * rsqrt(degree); also re-zero g_deg ----------------------
// One thread per node: read 64B fp32 row, write 32B bf16 row.
__global__ void k_scale(const float4* __restrict__ y4, int N) {
    int n = blockIdx.x * blockDim.x + threadIdx.x;
    if (n >= N) return;
    float s = rsqrtf(g_deg[n]);
    g_deg[n] = 0.0f;                      // restore invariant for next replay
    float4 u0 = __ldg(y4 + 4 * n + 0);
    float4 u1 = __ldg(y4 + 4 * n + 1);
    float4 u2 = __ldg(y4 + 4 * n + 2);
    float4 u3 = __ldg(y4 + 4 * n + 3);
    __nv_bfloat162 p0 = __float22bfloat162_rn(make_float2(u0.x * s, u0.y * s));
    __nv_bfloat162 p1 = __float22bfloat162_rn(make_float2(u0.z * s, u0.w * s));
    __nv_bfloat162 p2 = __float22bfloat162_rn(make_float2(u1.x * s, u1.y * s));
    __nv_bfloat162 p3 = __float22bfloat162_rn(make_float2(u1.z * s, u1.w * s));
    __nv_bfloat162 p4 = __float22bfloat162_rn(make_float2(u2.x * s, u2.y * s));
    __nv_bfloat162 p5 = __float22bfloat162_rn(make_float2(u2.z * s, u2.w * s));
    __nv_bfloat162 p6 = __float22bfloat162_rn(make_float2(u3.x * s, u3.y * s));
    __nv_bfloat162 p7 = __float22bfloat162_rn(make_float2(u3.z * s, u3.w * s));
    uint4 o0, o1;
    o0.x = *(unsigned*)&p0; o0.y = *(unsigned*)&p1;
    o0.z = *(unsigned*)&p2; o0.w = *(unsigned*)&p3;
    o1.x = *(unsigned*)&p4; o1.y = *(unsigned*)&p5;
    o1.z = *(unsigned*)&p6; o1.w = *(unsigned*)&p7;
    g_ysb[2 * n + 0] = o0;
    g_ysb[2 * n + 1] = o1;
}

// --- K3: octet-gather per-edge norm + reduce + finalize -------------------------
// Warp handles 16 edges. Lanes 0-15 load r/c/w for edges [wbase, wbase+16)
// (coalesced, 1 wavefront each). Gather phase: octet k (lanes 8k..8k+7)
// handles edges wbase+4k+u (u=0..3); each lane loads one bf16x2 (4B) of the
// 32B row -> each gather instruction touches exactly 4 cache lines.
#define EDGES_PER_BLOCK 128   // 8 warps x 16 edges

__global__ void __launch_bounds__(256)
k_main(const void* __restrict__ ei,
       const float* __restrict__ w,
       float* __restrict__ out, int E, int N, int nblocks) {
    const bool is32 = (g_flag != 0u);
    const int lane  = threadIdx.x & 31;
    const int warp  = threadIdx.x >> 5;
    const int oct   = lane >> 3;      // 0..3
    const int j     = lane & 7;       // component pair within row

    const long long wbase = (long long)blockIdx.x * EDGES_PER_BLOCK + warp * 16;

    // lanes 0..15 own edge wbase+lane
    int   myr = 0, myc = 0;
    float myw = 0.0f;
    if (lane < 16) {
        long long e = wbase + lane;
        if (e < (long long)E) {
            myr = load_idx(ei, e, is32);
            myc = load_idx(ei, (long long)E + e, is32);
            myw = __ldg(w + e);
            if ((unsigned)myr >= (unsigned)N || (unsigned)myc >= (unsigned)N) {
                myr = 0; myc = 0; myw = 0.0f;   // defensive: never trap
            }
        }
    }

    const unsigned* ys32 = (const unsigned*)g_ysb;   // row r at [r*8 .. r*8+8)

    // Issue all 8 gathers (4 unrolls x {row,col}) before any compute.
    unsigned a[4], b[4];
    #pragma unroll
    for (int u = 0; u < 4; u++) {
        int src = 4 * oct + u;                        // edge slot in [0,16)
        int r = __shfl_sync(0xFFFFFFFFu, myr, src);
        int c = __shfl_sync(0xFFFFFFFFu, myc, src);
        a[u] = ys32[(unsigned)r * 8u + j];
        b[u] = ys32[(unsigned)c * 8u + j];
    }

    float val = 0.0f;
    #pragma unroll
    for (int u = 0; u < 4; u++) {
        __nv_bfloat162 d = __hsub2(*(__nv_bfloat162*)&a[u], *(__nv_bfloat162*)&b[u]);
        float2 f = __bfloat1622float2(d);
        float acc = fmaf(f.x, f.x, f.y * f.y);
        // octet reduce -> full 16-component norm^2
        acc += __shfl_xor_sync(0xFFFFFFFFu, acc, 1);
        acc += __shfl_xor_sync(0xFFFFFFFFu, acc, 2);
        acc += __shfl_xor_sync(0xFFFFFFFFu, acc, 4);
        float we = __shfl_sync(0xFFFFFFFFu, myw, 4 * oct + u);
        if (j == 0) val += sqrtf(acc) * we;
    }

    // warp + block reduce
    #pragma unroll
    for (int o = 16; o > 0; o >>= 1)
        val += __shfl_down_sync(0xFFFFFFFFu, val, o);

    __shared__ float s_warp[8];
    if (lane == 0) s_warp[warp] = val;
    __syncthreads();

    if (warp == 0) {
        val = (lane < (int)(blockDim.x >> 5)) ? s_warp[lane] : 0.0f;
        #pragma unroll
        for (int o = 4; o > 0; o >>= 1)
            val += __shfl_down_sync(0xFFFFFFFFu, val, o);
        if (lane == 0) {
            atomicAdd(&g_sum, (double)val);
            __threadfence();
            unsigned ticket = atomicInc(&g_count, 0xFFFFFFFFu);
            if (ticket == (unsigned)(nblocks - 1)) {
                *out = (float)(g_sum / (double)E);
                g_sum = 0.0;          // restore invariants for next replay
                g_count = 0u;
            }
        }
    }
}

extern "C" void kernel_launch(void* const* d_in, const int* in_sizes, int n_in,
                              void* d_out, int out_size) {
    const void*   ei  = d_in[0];
    const float*  w   = (const float*)d_in[1];
    const float4* y4  = (const float4*)d_in[2];
    float*        out = (float*)d_out;

    const int E = in_sizes[1];       // number of edges
    const int N = in_sizes[2] / 16;  // number of nodes

    const int T = 256;
    int blocksE = (E + T - 1) / T;
    int blocksS = (N + T - 1) / T;
    int blocksM = (E + EDGES_PER_BLOCK - 1) / EDGES_PER_BLOCK;

    k_probe <<<1, 32>>>((const unsigned*)ei, E);
    k_degree<<<blocksE, T>>>(ei, w, E, N);
    k_scale <<<blocksS, T>>>(y4, N);
    k_main  <<<blocksM, T>>>(ei, w, out, E, N, blocksM);
}